// round 17
// baseline (speedup 1.0000x reference)
#include <cuda_runtime.h>
#include <cuda_fp16.h>
#include <cstdint>

// Problem sizes (fixed).
#define NB  2048
#define DD  1024
#define HH  131072
#define CC  1024
#define SSZ 8192

// ---------------- scratch (device globals; no allocation allowed) -----------
__device__ __half g_Xh[NB * DD];               // X, fp16-rounded
__device__ __half g_Wgh[SSZ * DD];             // gathered W_hidden rows, fp16
__device__ float  g_bg[SSZ];                   // gathered b_hidden (exact fp32)
__device__ __half g_h[(size_t)NB * SSZ];       // relu hidden, fp16
__device__ int    g_idx[SSZ];                  // sample ids as int32
__device__ int    g_ids64;

#define DEVFN __device__ __forceinline__

DEVFN uint32_t smem_u32(const void* p) {
    uint32_t a;
    asm("{ .reg .u64 t; cvta.to.shared.u64 t, %1; cvt.u32.u64 %0, t; }"
        : "=r"(a) : "l"(p));
    return a;
}

DEVFN uint32_t pack2h(__half a, __half b) {
    return (uint32_t)__half_as_ushort(a) | ((uint32_t)__half_as_ushort(b) << 16);
}

// SW64 swizzle for 64-byte rows: XOR 16B-chunk bits [5:4] with row bits [8:7].
#define SWZ64(o) ((uint32_t)(o) ^ ((((uint32_t)(o)) >> 3) & 0x30u))

#define LDM4(r, addr) \
    asm volatile("ldmatrix.sync.aligned.m8n8.x4.shared.b16 {%0,%1,%2,%3}, [%4];" \
                 : "=r"((r)[0]), "=r"((r)[1]), "=r"((r)[2]), "=r"((r)[3]) \
                 : "r"(addr))

#define STS16(addr, v) \
    asm volatile("st.shared.v4.b32 [%0], {%1,%2,%3,%4};" \
                 :: "r"(addr), "r"((v).x), "r"((v).y), "r"((v).z), "r"((v).w))

DEVFN void mma16816(float* c, const uint32_t* a, uint32_t b0, uint32_t b1) {
    asm volatile(
        "mma.sync.aligned.m16n8k16.row.col.f32.f16.f16.f32 "
        "{%0,%1,%2,%3}, {%4,%5,%6,%7}, {%8,%9}, {%0,%1,%2,%3};"
        : "+f"(c[0]), "+f"(c[1]), "+f"(c[2]), "+f"(c[3])
        : "r"(a[0]), "r"(a[1]), "r"(a[2]), "r"(a[3]), "r"(b0), "r"(b1));
}

// ---------------- pre-pass kernels -------------------------------------------
__global__ void k_detect(const int* __restrict__ ids32) {
    if (threadIdx.x == 0) {
        int all0 = 1;
        for (int j = 1; j < 128; j += 2) all0 &= (ids32[j] == 0);
        g_ids64 = all0;
    }
}

// ids (int32 or int64) -> int32 table for the fused gather.
__global__ void k_cvtIdx(const void* __restrict__ idsp) {
    int s = blockIdx.x * blockDim.x + threadIdx.x;
    long long id = g_ids64 ? ((const long long*)idsp)[s] : (long long)((const int*)idsp)[s];
    g_idx[s] = (int)id;
}

__global__ void k_cvtX(const float4* __restrict__ X4) {
    int i = blockIdx.x * blockDim.x + threadIdx.x;
    float4 v = X4[i];
    ((uint2*)g_Xh)[i] = make_uint2(
        pack2h(__float2half_rn(v.x), __float2half_rn(v.y)),
        pack2h(__float2half_rn(v.z), __float2half_rn(v.w)));
}

__global__ void k_gatherWh(const float* __restrict__ Wh, const float* __restrict__ bh) {
    int s = blockIdx.x;
    long long id = g_idx[s];
    const float4* src = (const float4*)(Wh + (size_t)id * DD);
    uint2* dst = (uint2*)(g_Wgh + (size_t)s * DD);
    for (int j = threadIdx.x; j < DD / 4; j += blockDim.x) {
        float4 v = src[j];
        dst[j] = make_uint2(
            pack2h(__float2half_rn(v.x), __float2half_rn(v.y)),
            pack2h(__float2half_rn(v.z), __float2half_rn(v.w)));
    }
    if (threadIdx.x == 0) g_bg[s] = bh[id];
}

// ---------------- GEMM1: fp16 mma.sync, TN=128 (R12-proven) ------------------
// h = fp16(relu(X * Wg^T + bg)). CTA tile 128x128, BK=32 halfs, SW64 swizzle,
// double buffer, LDG.128->reg->STS.128 fill, 8 warps (4m x 2n), 2 CTAs/SM.
__global__ void __launch_bounds__(256, 2) k_gemm1(
    const __half* __restrict__ A, const __half* __restrict__ B,
    const float* __restrict__ bias, __half* __restrict__ outH,
    int K, int ldo)
{
    constexpr int TN = 128;
    constexpr int NJ  = TN / 32;
    constexpr int NF  = TN / 16;
    constexpr int NCB = TN / 64;
    constexpr uint32_t ASZ = 128 * 64;
    constexpr uint32_t BSZ = (uint32_t)TN * 64;
    constexpr uint32_t STG = ASZ + BSZ;

    extern __shared__ char dsm[];
    __shared__ float s_bias[TN];

    const int tid = threadIdx.x;
    const int wid = tid >> 5, lane = tid & 31;
    const int m0 = blockIdx.y * 128;
    const int n0 = blockIdx.x * TN;
    const uint32_t sbase = (smem_u32(dsm) + 1023u) & ~1023u;

    for (int j = tid; j < TN; j += 256) s_bias[j] = bias[n0 + j];

    uint32_t asoff[2];
    const __half* pA[2];
    #pragma unroll
    for (int j = 0; j < 2; j++) {
        int c = tid + j * 256, row = c >> 2, wi = c & 3;
        asoff[j] = SWZ64(row * 64 + wi * 16);
        pA[j] = A + (size_t)(m0 + row) * K + wi * 8;
    }
    uint32_t bsoff[NCB];
    const __half* pB[NCB];
    #pragma unroll
    for (int j = 0; j < NCB; j++) {
        int c = tid + j * 256, row = c >> 2, wi = c & 3;
        bsoff[j] = SWZ64(row * 64 + wi * 16);
        pB[j] = B + (size_t)(n0 + row) * K + wi * 8;
    }

    const int wm = wid >> 1, wn = wid & 1;
    const int rA = wm * 32 + (lane & 15);
    const int rB = wn * (TN / 2) + (lane & 15);
    const int kb = (lane >> 4) * 16;
    uint32_t aoff[2][2], boff[NJ][2];
    #pragma unroll
    for (int mi = 0; mi < 2; mi++)
        #pragma unroll
        for (int ks = 0; ks < 2; ks++)
            aoff[mi][ks] = SWZ64((rA + mi * 16) * 64 + ks * 32 + kb);
    #pragma unroll
    for (int nj = 0; nj < NJ; nj++)
        #pragma unroll
        for (int ks = 0; ks < 2; ks++)
            boff[nj][ks] = SWZ64((rB + nj * 16) * 64 + ks * 32 + kb);

    float acc[2][NF][4];
    #pragma unroll
    for (int i = 0; i < 2; i++)
        #pragma unroll
        for (int j = 0; j < NF; j++)
            #pragma unroll
            for (int q = 0; q < 4; q++) acc[i][j][q] = 0.0f;

    uint4 sA[2], sB[NCB];
    auto ldg = [&](int kt) {
        const size_t off = (size_t)kt * 32;
        #pragma unroll
        for (int j = 0; j < 2; j++) sA[j] = *(const uint4*)(pA[j] + off);
        #pragma unroll
        for (int j = 0; j < NCB; j++) sB[j] = *(const uint4*)(pB[j] + off);
    };
    auto sts = [&](int b) {
        const uint32_t s0 = sbase + (uint32_t)b * STG;
        #pragma unroll
        for (int j = 0; j < 2; j++) STS16(s0 + asoff[j], sA[j]);
        #pragma unroll
        for (int j = 0; j < NCB; j++) STS16(s0 + ASZ + bsoff[j], sB[j]);
    };

    const int KT = K >> 5;
    ldg(0);
    sts(0);
    __syncthreads();

    for (int kt = 0; kt < KT; kt++) {
        const bool more = (kt + 1 < KT);
        if (more) ldg(kt + 1);

        const uint32_t s0 = sbase + (uint32_t)(kt & 1) * STG;
        const uint32_t tA = s0, tB = s0 + ASZ;

        #pragma unroll
        for (int ks = 0; ks < 2; ks++) {
            uint32_t a[2][4];
            #pragma unroll
            for (int mi = 0; mi < 2; mi++) LDM4(a[mi], tA + aoff[mi][ks]);
            #pragma unroll
            for (int nj = 0; nj < NJ; nj++) {
                uint32_t bb[4];
                LDM4(bb, tB + boff[nj][ks]);
                #pragma unroll
                for (int mi = 0; mi < 2; mi++) {
                    #pragma unroll
                    for (int p = 0; p < 2; p++)
                        mma16816(acc[mi][nj * 2 + p], a[mi], bb[p], bb[p + 2]);
                }
            }
        }
        if (more) sts((kt + 1) & 1);
        __syncthreads();
    }

    const int er = lane >> 2;
    const int ec = 2 * (lane & 3);
    #pragma unroll
    for (int mi = 0; mi < 2; mi++) {
        const int row = m0 + wm * 32 + mi * 16 + er;
        #pragma unroll
        for (int nf = 0; nf < NF; nf++) {
            const int colL = wn * (TN / 2) + nf * 8 + ec;
            const size_t o0 = (size_t)row * ldo + (size_t)(n0 + colL);
            const size_t o1 = o0 + (size_t)8 * ldo;
            float v0 = acc[mi][nf][0] + s_bias[colL];
            float v1 = acc[mi][nf][1] + s_bias[colL + 1];
            float v2 = acc[mi][nf][2] + s_bias[colL];
            float v3 = acc[mi][nf][3] + s_bias[colL + 1];
            *(uint32_t*)(outH + o0) = pack2h(
                __float2half_rn(fmaxf(v0, 0.0f)), __float2half_rn(fmaxf(v1, 0.0f)));
            *(uint32_t*)(outH + o1) = pack2h(
                __float2half_rn(fmaxf(v2, 0.0f)), __float2half_rn(fmaxf(v3, 0.0f)));
        }
    }
}

// ---------------- GEMM2 with FUSED column gather -----------------------------
// out[N=2048, C=1024] = h[N, S] * (Wo[:, ids])^T + b_out. TN=64, BK=32.
// B-stage loads Wo[c][idx[k]] directly (8 scattered 4B LDGs + cvt per thread
// per k-tile) instead of a pre-gathered tile. 256 CTAs = ONE wave at 2/SM, so
// the 16 y-blocks sharing each B tile run concurrently -> 15/16 of the
// scattered reads hit L2; DRAM sees the gather's irreducible 268 MB once,
// hidden under the tensor-bound mainloop.
__global__ void __launch_bounds__(256, 2) k_gemm2(
    const __half* __restrict__ A, const float* __restrict__ Wo,
    const float* __restrict__ bias, float* __restrict__ outF,
    int K, int ldo)
{
    constexpr int TN = 64;
    constexpr int NJ  = TN / 32;                // 2
    constexpr int NF  = TN / 16;                // 4
    constexpr uint32_t ASZ = 128 * 64;
    constexpr uint32_t BSZ = (uint32_t)TN * 64;
    constexpr uint32_t STG = ASZ + BSZ;

    extern __shared__ char dsm[];
    __shared__ float s_bias[TN];

    const int tid = threadIdx.x;
    const int wid = tid >> 5, lane = tid & 31;
    const int m0 = blockIdx.y * 128;
    const int n0 = blockIdx.x * TN;
    const uint32_t sbase = (smem_u32(dsm) + 1023u) & ~1023u;

    for (int j = tid; j < TN; j += 256) s_bias[j] = bias[n0 + j];

    // A-fill descriptors (h, K-major rows).
    uint32_t asoff[2];
    const __half* pA[2];
    #pragma unroll
    for (int j = 0; j < 2; j++) {
        int c = tid + j * 256, row = c >> 2, wi = c & 3;
        asoff[j] = SWZ64(row * 64 + wi * 16);
        pA[j] = A + (size_t)(m0 + row) * K + wi * 8;
    }
    // B-fill (fused gather): thread -> B row r = tid>>2 (c = n0+r), word wi.
    const int rB_ = tid >> 2, wiB = tid & 3;
    const uint32_t bsoff0 = SWZ64(rB_ * 64 + wiB * 16);
    const float* pWrow = Wo + (size_t)(n0 + rB_) * HH;

    const int wm = wid >> 1, wn = wid & 1;
    const int rA = wm * 32 + (lane & 15);
    const int rB = wn * (TN / 2) + (lane & 15);
    const int kb = (lane >> 4) * 16;
    uint32_t aoff[2][2], boff[NJ][2];
    #pragma unroll
    for (int mi = 0; mi < 2; mi++)
        #pragma unroll
        for (int ks = 0; ks < 2; ks++)
            aoff[mi][ks] = SWZ64((rA + mi * 16) * 64 + ks * 32 + kb);
    #pragma unroll
    for (int nj = 0; nj < NJ; nj++)
        #pragma unroll
        for (int ks = 0; ks < 2; ks++)
            boff[nj][ks] = SWZ64((rB + nj * 16) * 64 + ks * 32 + kb);

    float acc[2][NF][4];
    #pragma unroll
    for (int i = 0; i < 2; i++)
        #pragma unroll
        for (int j = 0; j < NF; j++)
            #pragma unroll
            for (int q = 0; q < 4; q++) acc[i][j][q] = 0.0f;

    uint4 sA[2];
    float bV[8];

    auto ldg = [&](int kt) {
        const size_t off = (size_t)kt * 32;
        #pragma unroll
        for (int j = 0; j < 2; j++) sA[j] = *(const uint4*)(pA[j] + off);
        const int kk = kt * 32 + wiB * 8;
        int4 i0 = *(const int4*)(g_idx + kk);
        int4 i1 = *(const int4*)(g_idx + kk + 4);
        bV[0] = pWrow[i0.x]; bV[1] = pWrow[i0.y];
        bV[2] = pWrow[i0.z]; bV[3] = pWrow[i0.w];
        bV[4] = pWrow[i1.x]; bV[5] = pWrow[i1.y];
        bV[6] = pWrow[i1.z]; bV[7] = pWrow[i1.w];
    };
    auto sts = [&](int b) {
        const uint32_t s0 = sbase + (uint32_t)b * STG;
        #pragma unroll
        for (int j = 0; j < 2; j++) STS16(s0 + asoff[j], sA[j]);
        uint4 bq;
        bq.x = pack2h(__float2half_rn(bV[0]), __float2half_rn(bV[1]));
        bq.y = pack2h(__float2half_rn(bV[2]), __float2half_rn(bV[3]));
        bq.z = pack2h(__float2half_rn(bV[4]), __float2half_rn(bV[5]));
        bq.w = pack2h(__float2half_rn(bV[6]), __float2half_rn(bV[7]));
        STS16(s0 + ASZ + bsoff0, bq);
    };

    const int KT = K >> 5;
    ldg(0);
    sts(0);
    __syncthreads();

    for (int kt = 0; kt < KT; kt++) {
        const bool more = (kt + 1 < KT);
        if (more) ldg(kt + 1);

        const uint32_t s0 = sbase + (uint32_t)(kt & 1) * STG;
        const uint32_t tA = s0, tB = s0 + ASZ;

        #pragma unroll
        for (int ks = 0; ks < 2; ks++) {
            uint32_t a[2][4];
            #pragma unroll
            for (int mi = 0; mi < 2; mi++) LDM4(a[mi], tA + aoff[mi][ks]);
            #pragma unroll
            for (int nj = 0; nj < NJ; nj++) {
                uint32_t bb[4];
                LDM4(bb, tB + boff[nj][ks]);
                #pragma unroll
                for (int mi = 0; mi < 2; mi++) {
                    #pragma unroll
                    for (int p = 0; p < 2; p++)
                        mma16816(acc[mi][nj * 2 + p], a[mi], bb[p], bb[p + 2]);
                }
            }
        }
        if (more) sts((kt + 1) & 1);
        __syncthreads();
    }

    const int er = lane >> 2;
    const int ec = 2 * (lane & 3);
    #pragma unroll
    for (int mi = 0; mi < 2; mi++) {
        const int row = m0 + wm * 32 + mi * 16 + er;
        #pragma unroll
        for (int nf = 0; nf < NF; nf++) {
            const int colL = wn * (TN / 2) + nf * 8 + ec;
            const size_t o0 = (size_t)row * ldo + (size_t)(n0 + colL);
            const size_t o1 = o0 + (size_t)8 * ldo;
            *(float2*)(outF + o0) = make_float2(acc[mi][nf][0] + s_bias[colL],
                                                acc[mi][nf][1] + s_bias[colL + 1]);
            *(float2*)(outF + o1) = make_float2(acc[mi][nf][2] + s_bias[colL],
                                                acc[mi][nf][3] + s_bias[colL + 1]);
        }
    }
}

// ---------------- launch -----------------------------------------------------
extern "C" void kernel_launch(void* const* d_in, const int* in_sizes, int n_in,
                              void* d_out, int out_size) {
    const float* X   = (const float*)d_in[0];
    const float* Wh  = (const float*)d_in[1];
    const float* bh  = (const float*)d_in[2];
    const float* Wo  = (const float*)d_in[3];
    const float* bo  = (const float*)d_in[4];
    const void*  ids = d_in[5];
    float* out = (float*)d_out;
    (void)in_sizes; (void)n_in; (void)out_size;

    void *pXh, *pWgh, *pbg, *ph;
    cudaGetSymbolAddress(&pXh, g_Xh);
    cudaGetSymbolAddress(&pWgh, g_Wgh);
    cudaGetSymbolAddress(&pbg, g_bg);
    cudaGetSymbolAddress(&ph, g_h);

    const int smem1 = 2 * (8192 + 128 * 64) + 1024;  // 33792
    const int smem2 = 2 * (8192 + 64 * 64) + 1024;   // 25600
    cudaFuncSetAttribute(k_gemm1, cudaFuncAttributeMaxDynamicSharedMemorySize, smem1);
    cudaFuncSetAttribute(k_gemm2, cudaFuncAttributeMaxDynamicSharedMemorySize, smem2);

    k_detect<<<1, 32>>>((const int*)ids);
    k_cvtIdx<<<SSZ / 256, 256>>>(ids);
    k_cvtX<<<(NB * DD / 4) / 256, 256>>>((const float4*)X);
    k_gatherWh<<<SSZ, 128>>>(Wh, bh);

    // GEMM1: h = fp16(relu(X * Wg^T + bg)). M=2048, N=8192, K=1024. TN=128.
    k_gemm1<<<dim3(SSZ / 128, NB / 128), 256, smem1>>>(
        (const __half*)pXh, (const __half*)pWgh, (const float*)pbg,
        (__half*)ph, DD, SSZ);

    // GEMM2 (fused gather): out = h * Wo[:,ids]^T + b_out. M=2048, N=1024, K=8192.
    k_gemm2<<<dim3(CC / 64, NB / 128), 256, smem2>>>(
        (const __half*)ph, Wo, bo, out, SSZ, CC);
}